// round 1
// baseline (speedup 1.0000x reference)
#include <cuda_runtime.h>
#include <cuda_bf16.h>

#define DIMK    2048
#define NEXP    64
#define BM      128
#define KC      64
#define TM      8
#define TN      8
#define NTHREADS 128

// ---------- packed f32x2 helpers (Blackwell PTX) ----------
__device__ __forceinline__ unsigned long long pack2(float lo, float hi) {
    unsigned long long r;
    asm("mov.b64 %0, {%1, %2};" : "=l"(r) : "f"(lo), "f"(hi));
    return r;
}
__device__ __forceinline__ void unpack2(unsigned long long v, float& lo, float& hi) {
    asm("mov.b64 {%0, %1}, %2;" : "=f"(lo), "=f"(hi) : "l"(v));
}
__device__ __forceinline__ unsigned long long fma2(unsigned long long a,
                                                   unsigned long long b,
                                                   unsigned long long c) {
    unsigned long long d;
    asm("fma.rn.f32x2 %0, %1, %2, %3;" : "=l"(d) : "l"(a), "l"(b), "l"(c));
    return d;
}
__device__ __forceinline__ unsigned long long add2(unsigned long long a,
                                                   unsigned long long b) {
    unsigned long long d;
    asm("add.rn.f32x2 %0, %1, %2;" : "=l"(d) : "l"(a), "l"(b));
    return d;
}

// Tile: 128 tokens x 64 experts per block, K-chunks of 64.
// 128 threads, each computes 8 tokens x 8 experts (experts packed as f32x2 pairs).
__global__ __launch_bounds__(NTHREADS, 2)
void router_kernel(const float* __restrict__ x,
                   const float* __restrict__ w,
                   float* __restrict__ out_mask,
                   float* __restrict__ out_w,
                   float* __restrict__ out_i)
{
    // As[KC][BM] (transposed x tile)  = 8192 floats
    // Bs[KC][NEXP] (transposed w tile)= 4096 floats   -> 48KB total (also reused for epilogue)
    __shared__ __align__(16) float sm[KC * BM + KC * NEXP];
    float* As = sm;
    float* Bs = sm + KC * BM;

    const int tid  = threadIdx.x;
    const int lane = tid & 31;
    const int warp = tid >> 5;
    const int tx   = tid & 15;   // token group: tokens tx*8 .. tx*8+7
    const int ty   = tid >> 4;   // expert group: experts ty*8 .. ty*8+7
    const int mbase = blockIdx.x * BM;

    // main accumulators: [token j][expert pair p], each u64 = 2 fp32 (experts 2p, 2p+1)
    unsigned long long accm[TM][TN / 2];
#pragma unroll
    for (int j = 0; j < TM; j++)
#pragma unroll
        for (int p = 0; p < TN / 2; p++)
            accm[j][p] = 0ULL;

    // Tile load assignment (lane == row mod 32 -> conflict-free transposed STS)
    const int a_row = tid;                       // 0..127
    const int b_row = (warp & 1) * 32 + lane;    // 0..63
    const int b_segbase = (warp >> 1) * 8;       // 0 or 8 (float4 segments)

    const float4* xg = (const float4*)(x + (size_t)(mbase + a_row) * DIMK);
    const float4* wg = (const float4*)(w + (size_t)b_row * DIMK);

    for (int kt = 0; kt < DIMK; kt += KC) {
        __syncthreads();
        const int segk = kt >> 2;  // float4 index of chunk start

        // x tile -> As[k][m] (each thread owns one token row; 16 float4 segments)
#pragma unroll
        for (int s = 0; s < 16; s++) {
            float4 v = xg[segk + s];
            As[(s * 4 + 0) * BM + a_row] = v.x;
            As[(s * 4 + 1) * BM + a_row] = v.y;
            As[(s * 4 + 2) * BM + a_row] = v.z;
            As[(s * 4 + 3) * BM + a_row] = v.w;
        }
        // w tile -> Bs[k][e] (each thread owns one expert row; 8 segments)
#pragma unroll
        for (int s = 0; s < 8; s++) {
            int seg = b_segbase + s;
            float4 v = wg[segk + seg];
            Bs[(seg * 4 + 0) * NEXP + b_row] = v.x;
            Bs[(seg * 4 + 1) * NEXP + b_row] = v.y;
            Bs[(seg * 4 + 2) * NEXP + b_row] = v.z;
            Bs[(seg * 4 + 3) * NEXP + b_row] = v.w;
        }
        __syncthreads();

        // chunk accumulators (two-level sum for fp32 accuracy)
        unsigned long long accc[TM][TN / 2];
#pragma unroll
        for (int j = 0; j < TM; j++)
#pragma unroll
            for (int p = 0; p < TN / 2; p++)
                accc[j][p] = 0ULL;

#pragma unroll 16
        for (int k = 0; k < KC; k++) {
            const float* ar = As + k * BM + tx * TM;
            float4 a0 = *(const float4*)(ar);
            float4 a1 = *(const float4*)(ar + 4);
            const unsigned long long* bp =
                (const unsigned long long*)(Bs + k * NEXP + ty * TN);
            unsigned long long b0 = bp[0], b1 = bp[1], b2 = bp[2], b3 = bp[3];
            float av[TM] = {a0.x, a0.y, a0.z, a0.w, a1.x, a1.y, a1.z, a1.w};
#pragma unroll
            for (int j = 0; j < TM; j++) {
                unsigned long long ad = pack2(av[j], av[j]);
                accc[j][0] = fma2(ad, b0, accc[j][0]);
                accc[j][1] = fma2(ad, b1, accc[j][1]);
                accc[j][2] = fma2(ad, b2, accc[j][2]);
                accc[j][3] = fma2(ad, b3, accc[j][3]);
            }
        }

#pragma unroll
        for (int j = 0; j < TM; j++)
#pragma unroll
            for (int p = 0; p < TN / 2; p++)
                accm[j][p] = add2(accm[j][p], accc[j][p]);
    }

    // ---------------- epilogue: top-2 + softmax + mask ----------------
    __syncthreads();
    // logits tile L[m][e] with stride 65 (conflict-free row scans), reuse sm
    float* L = sm;
#pragma unroll
    for (int j = 0; j < TM; j++) {
        int m = tx * TM + j;
#pragma unroll
        for (int p = 0; p < TN / 2; p++) {
            float lo, hi;
            unpack2(accm[j][p], lo, hi);
            L[m * 65 + ty * TN + 2 * p]     = lo;
            L[m * 65 + ty * TN + 2 * p + 1] = hi;
        }
    }
    __syncthreads();

    int* ti = (int*)(sm + BM * 65);  // [BM][2] top-2 indices, fits in the 48KB

    if (tid < BM) {
        const float* row = L + tid * 65;
        float v0 = -1e30f, v1 = -1e30f;
        int   i0 = 0,      i1 = 0;
#pragma unroll
        for (int e = 0; e < NEXP; e++) {
            float l = row[e];
            if (l > v0) { v1 = v0; i1 = i0; v0 = l; i0 = e; }
            else if (l > v1) { v1 = l; i1 = e; }
        }
        float e1 = expf(v1 - v0);       // <= 1
        float inv = 1.0f / (1.0f + e1);
        float w0 = inv;
        float w1 = e1 * inv;
        size_t g = (size_t)(mbase + tid);
        out_w[g * 2 + 0] = w0;
        out_w[g * 2 + 1] = w1;
        out_i[g * 2 + 0] = (float)i0;
        out_i[g * 2 + 1] = (float)i1;
        ti[tid * 2 + 0] = i0;
        ti[tid * 2 + 1] = i1;
    }
    __syncthreads();

    // one-hot mask, coalesced writes
    for (int idx = tid; idx < BM * NEXP; idx += NTHREADS) {
        int m = idx >> 6;
        int e = idx & 63;
        int a = ti[m * 2], b = ti[m * 2 + 1];
        out_mask[(size_t)(mbase + m) * NEXP + e] = (e == a || e == b) ? 1.0f : 0.0f;
    }
}

extern "C" void kernel_launch(void* const* d_in, const int* in_sizes, int n_in,
                              void* d_out, int out_size) {
    const float* x = (const float*)d_in[0];   // (N, 2048) fp32
    const float* w = (const float*)d_in[1];   // (64, 2048) fp32
    int n_tokens = in_sizes[0] / DIMK;        // 32768

    float* out      = (float*)d_out;
    float* out_mask = out;                                   // N*64
    float* out_w    = out + (size_t)n_tokens * NEXP;         // N*2
    float* out_i    = out_w + (size_t)n_tokens * 2;          // N*2 (indices as float)

    int grid = n_tokens / BM;                 // 256 blocks
    router_kernel<<<grid, NTHREADS>>>(x, w, out_mask, out_w, out_i);
}

// round 2
// speedup vs baseline: 1.0896x; 1.0896x over previous
#include <cuda_runtime.h>
#include <cuda_bf16.h>

#define DIMK    2048
#define NEXP    64
#define BM      128
#define KC      64
#define TM      8
#define TN      8
#define NTHREADS 128

// ---------- packed f32x2 helpers (Blackwell PTX) ----------
__device__ __forceinline__ unsigned long long pack2(float lo, float hi) {
    unsigned long long r;
    asm("mov.b64 %0, {%1, %2};" : "=l"(r) : "f"(lo), "f"(hi));
    return r;
}
__device__ __forceinline__ void unpack2(unsigned long long v, float& lo, float& hi) {
    asm("mov.b64 {%0, %1}, %2;" : "=f"(lo), "=f"(hi) : "l"(v));
}
__device__ __forceinline__ unsigned long long fma2(unsigned long long a,
                                                   unsigned long long b,
                                                   unsigned long long c) {
    unsigned long long d;
    asm("fma.rn.f32x2 %0, %1, %2, %3;" : "=l"(d) : "l"(a), "l"(b), "l"(c));
    return d;
}
__device__ __forceinline__ unsigned long long add2(unsigned long long a,
                                                   unsigned long long b) {
    unsigned long long d;
    asm("add.rn.f32x2 %0, %1, %2;" : "=l"(d) : "l"(a), "l"(b));
    return d;
}

// Tile: 128 tokens x 64 experts per block, K-chunks of 64.
// 128 threads, 8 tokens x 8 experts per thread.
// Warp-square mapping: each warp covers 64 tokens x 32 experts
// -> 4 conflict-free LDS wavefronts per warp per k-step.
__global__ __launch_bounds__(NTHREADS, 2)
void router_kernel(const float* __restrict__ x,
                   const float* __restrict__ w,
                   float* __restrict__ out_mask,
                   float* __restrict__ out_w,
                   float* __restrict__ out_i)
{
    // As[KC][BM] (transposed x tile) = 8192 floats
    // Bs[KC][NEXP] (transposed w tile) = 4096 floats  -> 48KB (reused in epilogue)
    __shared__ __align__(16) float sm[KC * BM + KC * NEXP];
    float* As = sm;
    float* Bs = sm + KC * BM;

    const int tid  = threadIdx.x;
    const int lane = tid & 31;
    const int warp = tid >> 5;

    // warp-square fragment mapping
    const int tx_l = lane & 7;        // token group within warp (8)
    const int ty_l = lane >> 3;       // expert group within warp (4)
    const int wx   = warp & 1;
    const int wy   = warp >> 1;
    const int tx   = wx * 8 + tx_l;   // 0..15  (token group of 4+4)
    const int ty   = wy * 4 + ty_l;   // 0..7   (expert group of 4+4)

    const int mbase = blockIdx.x * BM;

    // main accumulators: [token j][expert pair p] (pairs: 2 per B half)
    unsigned long long accm[TM][TN / 2];
#pragma unroll
    for (int j = 0; j < TM; j++)
#pragma unroll
        for (int p = 0; p < TN / 2; p++)
            accm[j][p] = 0ULL;

    // tile-load assignment (conflict-free transposed STS)
    const int a_row = tid;                       // 0..127
    const int b_row = (warp & 1) * 32 + lane;    // 0..63
    const int b_segbase = (warp >> 1) * 8;       // 0 or 8 (float4 segments)

    const float4* xg = (const float4*)(x + (size_t)(mbase + a_row) * DIMK);
    const float4* wg = (const float4*)(w + (size_t)b_row * DIMK);

    for (int kt = 0; kt < DIMK; kt += KC) {
        __syncthreads();
        const int segk = kt >> 2;

        // x tile -> As[k][m]
#pragma unroll
        for (int s = 0; s < 16; s++) {
            float4 v = xg[segk + s];
            As[(s * 4 + 0) * BM + a_row] = v.x;
            As[(s * 4 + 1) * BM + a_row] = v.y;
            As[(s * 4 + 2) * BM + a_row] = v.z;
            As[(s * 4 + 3) * BM + a_row] = v.w;
        }
        // w tile -> Bs[k][e]
#pragma unroll
        for (int s = 0; s < 8; s++) {
            int seg = b_segbase + s;
            float4 v = wg[segk + seg];
            Bs[(seg * 4 + 0) * NEXP + b_row] = v.x;
            Bs[(seg * 4 + 1) * NEXP + b_row] = v.y;
            Bs[(seg * 4 + 2) * NEXP + b_row] = v.z;
            Bs[(seg * 4 + 3) * NEXP + b_row] = v.w;
        }
        __syncthreads();

        // chunk accumulators (two-level fp32 accumulation)
        unsigned long long accc[TM][TN / 2];
#pragma unroll
        for (int j = 0; j < TM; j++)
#pragma unroll
            for (int p = 0; p < TN / 2; p++)
                accc[j][p] = 0ULL;

#pragma unroll 8
        for (int k = 0; k < KC; k++) {
            const float* ar = As + k * BM + tx * 4;
            float4 a0 = *(const float4*)(ar);          // tokens tx*4 .. +3
            float4 a1 = *(const float4*)(ar + 64);     // tokens 64+tx*4 .. +3
            const float* br = Bs + k * NEXP + ty * 4;
            ulonglong2 b0 = *(const ulonglong2*)(br);        // experts ty*4..+3
            ulonglong2 b1 = *(const ulonglong2*)(br + 32);   // experts 32+ty*4..+3
            float av[TM] = {a0.x, a0.y, a0.z, a0.w, a1.x, a1.y, a1.z, a1.w};
#pragma unroll
            for (int j = 0; j < TM; j++) {
                unsigned long long ad = pack2(av[j], av[j]);
                accc[j][0] = fma2(ad, b0.x, accc[j][0]);
                accc[j][1] = fma2(ad, b0.y, accc[j][1]);
                accc[j][2] = fma2(ad, b1.x, accc[j][2]);
                accc[j][3] = fma2(ad, b1.y, accc[j][3]);
            }
        }

#pragma unroll
        for (int j = 0; j < TM; j++)
#pragma unroll
            for (int p = 0; p < TN / 2; p++)
                accm[j][p] = add2(accm[j][p], accc[j][p]);
    }

    // ---------------- epilogue: top-2 + softmax + mask ----------------
    __syncthreads();
    // logits tile L[m][e] stride 65 (conflict-free row scans), reuse sm
    float* L = sm;
#pragma unroll
    for (int j = 0; j < TM; j++) {
        int m = (j < 4) ? (tx * 4 + j) : (64 + tx * 4 + (j - 4));
#pragma unroll
        for (int p = 0; p < TN / 2; p++) {
            int e = (p < 2) ? (ty * 4 + 2 * p) : (32 + ty * 4 + 2 * (p - 2));
            float lo, hi;
            unpack2(accm[j][p], lo, hi);
            L[m * 65 + e]     = lo;
            L[m * 65 + e + 1] = hi;
        }
    }
    __syncthreads();

    int* ti = (int*)(sm + BM * 65);  // [BM][2] top-2 indices

    if (tid < BM) {
        const float* row = L + tid * 65;
        float v0 = -1e30f, v1 = -1e30f;
        int   i0 = 0,      i1 = 0;
#pragma unroll
        for (int e = 0; e < NEXP; e++) {
            float l = row[e];
            if (l > v0) { v1 = v0; i1 = i0; v0 = l; i0 = e; }
            else if (l > v1) { v1 = l; i1 = e; }
        }
        float e1 = expf(v1 - v0);
        float inv = 1.0f / (1.0f + e1);
        size_t g = (size_t)(mbase + tid);
        out_w[g * 2 + 0] = inv;
        out_w[g * 2 + 1] = e1 * inv;
        out_i[g * 2 + 0] = (float)i0;
        out_i[g * 2 + 1] = (float)i1;
        ti[tid * 2 + 0] = i0;
        ti[tid * 2 + 1] = i1;
    }
    __syncthreads();

    // one-hot mask, coalesced
    for (int idx = tid; idx < BM * NEXP; idx += NTHREADS) {
        int m = idx >> 6;
        int e = idx & 63;
        int a = ti[m * 2], b = ti[m * 2 + 1];
        out_mask[(size_t)(mbase + m) * NEXP + e] = (e == a || e == b) ? 1.0f : 0.0f;
    }
}

extern "C" void kernel_launch(void* const* d_in, const int* in_sizes, int n_in,
                              void* d_out, int out_size) {
    const float* x = (const float*)d_in[0];   // (N, 2048) fp32
    const float* w = (const float*)d_in[1];   // (64, 2048) fp32
    int n_tokens = in_sizes[0] / DIMK;        // 32768

    float* out      = (float*)d_out;
    float* out_mask = out;                                   // N*64
    float* out_w    = out + (size_t)n_tokens * NEXP;         // N*2
    float* out_i    = out_w + (size_t)n_tokens * 2;          // N*2

    int grid = n_tokens / BM;                 // 256 blocks
    router_kernel<<<grid, NTHREADS>>>(x, w, out_mask, out_w, out_i);
}